// round 8
// baseline (speedup 1.0000x reference)
#include <cuda_runtime.h>

// LUT tree, monomial-coefficient form + cp.async staged x.
// 512-thread CTAs (2/SM, 64-reg cap), one row per warp, 16-row tiles.
// x flows GMEM -> smem via cp.async.cg (L1 bypass), 3-stage pipeline with
// one __syncthreads per batch; 2 groups (128 lines/CTA) in flight during
// compute. Persistent CTAs steal tiles from a global counter; the next tile's
// first two batches are issued before the current tile's tail layers run.

#define THREADS  512
#define NWARPS   16
#define GRID     296                 // 2 CTAs/SM * 148 SMs
#define ROWS_PT  16                  // rows per CTA tile

#define NODE_F   20                  // 16 monomial coefs + 4 pad (80B stride)
#define N_NODES  341
#define TTOT     (N_NODES * NODE_F)  // 6820 floats
#define STAGE_F  (ROWS_PT * 128)     // 2048 floats = 8KB per stage
#define NSTAGE   3
#define XCHF     (ROWS_PT * 256)     // 4096 floats
#define SMEM_F   (TTOT + NSTAGE * STAGE_F + XCHF + 4)
#define SMEM_B   (SMEM_F * 4)        // 68288 B

typedef unsigned uns;
__device__ uns g_ctr;
__global__ void reset_ctr() { g_ctr = 0; }

#define CP_COMMIT() asm volatile("cp.async.commit_group;\n" ::: "memory")
#define CP_WAIT1()  asm volatile("cp.async.wait_group 1;\n" ::: "memory")

__device__ __forceinline__ void issue_batch(float* stage_s, const float* x,
                                            uns tile, int b, int w, int lane) {
    // row w of tile, batch b (512B/row); this thread copies one 16B chunk
    unsigned dst = (unsigned)__cvta_generic_to_shared(stage_s + w * 128 + lane * 4);
    const float* src = x + ((size_t)tile * ROWS_PT + w) * 1024 + b * 128 + lane * 4;
    asm volatile("cp.async.cg.shared.global [%0], [%1], 16;\n"
                 :: "r"(dst), "l"(src));
}

// eval with monomial coefs c[16], index = b0 + 2b1 + 4b2 + 8b3 (bit i <-> x_i)
__device__ __forceinline__ float node_eval(const float* c, float4 xv) {
    float4 q0 = *(const float4*)(c + 0);
    float4 q1 = *(const float4*)(c + 4);
    float4 q2 = *(const float4*)(c + 8);
    float4 q3 = *(const float4*)(c + 12);
    float s0 = fmaf(xv.y, fmaf(xv.x, q0.w, q0.z), fmaf(xv.x, q0.y, q0.x));
    float s1 = fmaf(xv.y, fmaf(xv.x, q1.w, q1.z), fmaf(xv.x, q1.y, q1.x));
    float s2 = fmaf(xv.y, fmaf(xv.x, q2.w, q2.z), fmaf(xv.x, q2.y, q2.x));
    float s3 = fmaf(xv.y, fmaf(xv.x, q3.w, q3.z), fmaf(xv.x, q3.y, q3.x));
    return fmaf(xv.w, fmaf(xv.z, s3, s2), fmaf(xv.z, s1, s0));
}

__global__ void __launch_bounds__(THREADS, 2) lut_tree_kernel(
    const float* __restrict__ x,
    const float* __restrict__ t0, const float* __restrict__ t1,
    const float* __restrict__ t2, const float* __restrict__ t3,
    const float* __restrict__ t4,
    float* __restrict__ out, int nt)
{
    extern __shared__ __align__(16) float smem[];
    float* sh_t  = smem;                           // [341][20] monomial coefs
    float* stage = smem + TTOT;                    // [3][ROWS_PT][128]
    float* xch   = stage + NSTAGE * STAGE_F;       // [ROWS_PT][256]
    uns*   sh_nx = (uns*)(xch + XCHF);

    // ---- loader: fetch 16 corners per node, Mobius transform, store padded ----
    for (int g = threadIdx.x; g < N_NODES; g += THREADS) {
        const float* src; int ln;
        if (g < 256)      { src = t0; ln = g; }
        else if (g < 320) { src = t1; ln = g - 256; }
        else if (g < 336) { src = t2; ln = g - 320; }
        else if (g < 340) { src = t3; ln = g - 336; }
        else              { src = t4; ln = 0; }
        float v[16];
        #pragma unroll
        for (int k = 0; k < 16; ++k) v[k] = src[ln * 16 + k];
        #pragma unroll
        for (int i = 0; i < 4; ++i)
            #pragma unroll
            for (int c = 0; c < 16; ++c)
                if (c & (1 << i)) v[c] -= v[c ^ (1 << i)];
        float* dst = sh_t + g * NODE_F;
        #pragma unroll
        for (int k = 0; k < 16; ++k) dst[k] = v[k];
    }

    const int w    = threadIdx.x >> 5;
    const int lane = threadIdx.x & 31;
    const unsigned FULL = 0xffffffffu;

    if (threadIdx.x == 0) sh_nx[0] = atomicAdd(&g_ctr, 1);
    __syncthreads();                                // tables ready + steal visible
    uns t = sh_nx[0];
    if (t >= (uns)nt) return;                       // uniform across CTA

    // prologue: issue batches 0,1 of first tile
    issue_batch(stage + 0 * STAGE_F, x, t, 0, w, lane); CP_COMMIT();
    issue_batch(stage + 1 * STAGE_F, x, t, 1, w, lane); CP_COMMIT();

    int ip = 2;            // stage index for next issue
    int cphase = 0;        // stage index for next consume
    uns tn = 0xffffffffu;

    while (t < (uns)nt) {
        #pragma unroll
        for (int j = 0; j < 8; ++j) {
            CP_WAIT1();                 // own group j complete (<=1 pending)
            __syncthreads();            // whole stage j complete CTA-wide

            // issue batch j+2 (stage ip was last read two batches ago -> safe)
            if (j < 6) {
                issue_batch(stage + ip * STAGE_F, x, t, j + 2, w, lane);
            } else {
                if (j == 6) tn = sh_nx[0];          // published by sync above
                if (tn < (uns)nt)
                    issue_batch(stage + ip * STAGE_F, x, tn, j - 6, w, lane);
            }
            CP_COMMIT();
            ip = (ip + 1) % 3;

            if (j == 5 && threadIdx.x == 0)
                sh_nx[0] = atomicAdd(&g_ctr, 1);    // read after sync at j==6

            // compute batch j: lane computes layer-0 node 32j+lane of row w
            float4 xv = ((const float4*)(stage + cphase * STAGE_F))[w * 32 + lane];
            cphase = (cphase + 1) % 3;
            const float* cp = sh_t + (j * 32 + lane) * NODE_F;
            xch[w * 256 + j * 32 + lane] = node_eval(cp, xv);
        }
        __syncwarp();                   // own warp's xch row complete

        // ---- layers 1..4 for row w ----
        {
            const float* xr = xch + w * 256;
            float4 a0 = *(const float4*)(xr + lane * 8);
            float4 a1 = *(const float4*)(xr + lane * 8 + 4);
            float z0 = node_eval(sh_t + (256 + 2 * lane) * NODE_F, a0);
            float z1 = node_eval(sh_t + (256 + 2 * lane + 1) * NODE_F, a1);

            float4 b;
            b.x = __shfl_sync(FULL, z0, (lane * 2) & 31);
            b.y = __shfl_sync(FULL, z1, (lane * 2) & 31);
            b.z = __shfl_sync(FULL, z0, (lane * 2 + 1) & 31);
            b.w = __shfl_sync(FULL, z1, (lane * 2 + 1) & 31);
            float wv = node_eval(sh_t + (320 + (lane & 15)) * NODE_F, b);

            float4 c;
            c.x = __shfl_sync(FULL, wv, (lane * 4 + 0) & 31);
            c.y = __shfl_sync(FULL, wv, (lane * 4 + 1) & 31);
            c.z = __shfl_sync(FULL, wv, (lane * 4 + 2) & 31);
            c.w = __shfl_sync(FULL, wv, (lane * 4 + 3) & 31);
            float v = node_eval(sh_t + (336 + (lane & 3)) * NODE_F, c);

            float4 d;
            d.x = __shfl_sync(FULL, v, 0);
            d.y = __shfl_sync(FULL, v, 1);
            d.z = __shfl_sync(FULL, v, 2);
            d.w = __shfl_sync(FULL, v, 3);
            if (lane == 0)
                out[t * ROWS_PT + w] = node_eval(sh_t + 340 * NODE_F, d);
        }
        __syncwarp();                   // xch reads done before next tile writes

        t = tn;                         // uniform
    }
}

extern "C" void kernel_launch(void* const* d_in, const int* in_sizes, int n_in,
                              void* d_out, int out_size) {
    const float* x  = (const float*)d_in[0];
    const float* t0 = (const float*)d_in[1];
    const float* t1 = (const float*)d_in[2];
    const float* t2 = (const float*)d_in[3];
    const float* t3 = (const float*)d_in[4];
    const float* t4 = (const float*)d_in[5];
    float* out = (float*)d_out;

    int n_rows = in_sizes[0] / 1024;   // 32768
    int nt = n_rows / ROWS_PT;         // 2048 tiles

    reset_ctr<<<1, 1>>>();
    cudaFuncSetAttribute(lut_tree_kernel,
                         cudaFuncAttributeMaxDynamicSharedMemorySize, SMEM_B);
    lut_tree_kernel<<<GRID, THREADS, SMEM_B>>>(x, t0, t1, t2, t3, t4, out, nt);
}

// round 9
// speedup vs baseline: 1.1732x; 1.1732x over previous
#include <cuda_runtime.h>

// LUT tree, monomial-coefficient form (R7 structure, depth-2 ring, 3 CTAs/SM).
// Loader Mobius-transforms each 16-entry corner table into multilinear monomial
// coefficients -> node eval is 15 pure FMAs. Persistent warps steal 4-row tiles;
// layer-0 x loads prefetched 1 batch ahead through a 2-deep register ring
// (8 batches % 2 == 0 -> phase stable across tiles). Next tile stolen at j==7,
// its batch 0 loads under the tail layers. 85-reg cap -> 3 CTAs/SM, 24 warps.

#define THREADS  256
#define NWARPS   8
#define GRID     444            // 3 CTAs/SM * 148 SMs
#define G        4              // rows per tile

#define NODE_F   20             // 16 coefs + 4 pad -> 80B stride, conflict-free
#define N_NODES  341            // 256+64+16+4+1, by global node id g
#define TTOT     (N_NODES * NODE_F)
#define XCHF     (NWARPS * G * 256)
#define SMEM_B   ((TTOT + XCHF) * 4)   // 27280 + 32768 = 60048 B

typedef unsigned uns;
__device__ uns g_ctr;
__global__ void reset_ctr() { g_ctr = 0; }

// eval with monomial coefs c[16], index = b0 + 2b1 + 4b2 + 8b3 (bit i <-> x_i)
__device__ __forceinline__ float node_eval(const float* c, float4 xv) {
    float4 q0 = *(const float4*)(c + 0);
    float4 q1 = *(const float4*)(c + 4);
    float4 q2 = *(const float4*)(c + 8);
    float4 q3 = *(const float4*)(c + 12);
    float s0 = fmaf(xv.y, fmaf(xv.x, q0.w, q0.z), fmaf(xv.x, q0.y, q0.x));
    float s1 = fmaf(xv.y, fmaf(xv.x, q1.w, q1.z), fmaf(xv.x, q1.y, q1.x));
    float s2 = fmaf(xv.y, fmaf(xv.x, q2.w, q2.z), fmaf(xv.x, q2.y, q2.x));
    float s3 = fmaf(xv.y, fmaf(xv.x, q3.w, q3.z), fmaf(xv.x, q3.y, q3.x));
    return fmaf(xv.w, fmaf(xv.z, s3, s2), fmaf(xv.z, s1, s0));
}

__device__ __forceinline__ void load_batch(float4* B, const float4* xb, int j, int lane) {
    #pragma unroll
    for (int r = 0; r < G; ++r)
        B[r] = xb[r * 256 + j * 32 + lane];
}

__global__ void __launch_bounds__(THREADS, 3) lut_tree_kernel(
    const float* __restrict__ x,
    const float* __restrict__ t0, const float* __restrict__ t1,
    const float* __restrict__ t2, const float* __restrict__ t3,
    const float* __restrict__ t4,
    float* __restrict__ out, int nt)
{
    extern __shared__ __align__(16) float smem[];
    float* sh_t = smem;                 // [341][20] monomial coefs
    float* sh_x = smem + TTOT;          // [NWARPS][G][256] exchange

    // ---- loader: fetch 16 corners per node, Mobius transform, store padded ----
    for (int g = threadIdx.x; g < N_NODES; g += THREADS) {
        const float* src; int ln;
        if (g < 256)      { src = t0; ln = g; }
        else if (g < 320) { src = t1; ln = g - 256; }
        else if (g < 336) { src = t2; ln = g - 320; }
        else if (g < 340) { src = t3; ln = g - 336; }
        else              { src = t4; ln = 0; }
        float v[16];
        #pragma unroll
        for (int k = 0; k < 16; ++k) v[k] = src[ln * 16 + k];
        #pragma unroll
        for (int i = 0; i < 4; ++i)
            #pragma unroll
            for (int c = 0; c < 16; ++c)
                if (c & (1 << i)) v[c] -= v[c ^ (1 << i)];
        float* dst = sh_t + g * NODE_F;
        #pragma unroll
        for (int k = 0; k < 16; ++k) dst[k] = v[k];
    }
    __syncthreads();

    const int warp = threadIdx.x >> 5;
    const int lane = threadIdx.x & 31;
    const unsigned FULL = 0xffffffffu;
    float* xch = sh_x + warp * (G * 256);

    uns t;
    if (lane == 0) t = atomicAdd(&g_ctr, 1);
    t = __shfl_sync(FULL, t, 0);

    float4 B[2][G];                      // depth-2 ring: read B[j&1], write B[(j+1)&1]
    const float4* xb = (const float4*)x + (size_t)t * (G * 256);
    if (t < (uns)nt)
        load_batch(B[0], xb, 0, lane);

    while (t < (uns)nt) {
        uns tn = 0xffffffffu;
        const float4* xbn = xb;

        // ---- layer 0: prefetch 1 batch ahead, stream crosses into next tile ----
        #pragma unroll
        for (int j = 0; j < 8; ++j) {
            if (j < 7) {
                load_batch(B[(j + 1) & 1], xb, j + 1, lane);
            } else {
                if (lane == 0) tn = atomicAdd(&g_ctr, 1);
                tn = __shfl_sync(FULL, tn, 0);
                xbn = (const float4*)x + (size_t)tn * (G * 256);
                if (tn < (uns)nt)
                    load_batch(B[(j + 1) & 1], xbn, 0, lane);  // -> B[0], phase OK
            }
            const float* cp = sh_t + (j * 32 + lane) * NODE_F;
            float4 q0 = *(const float4*)(cp + 0);
            float4 q1 = *(const float4*)(cp + 4);
            float4 q2 = *(const float4*)(cp + 8);
            float4 q3 = *(const float4*)(cp + 12);
            #pragma unroll
            for (int r = 0; r < G; ++r) {
                float4 xv = B[j & 1][r];
                float s0 = fmaf(xv.y, fmaf(xv.x, q0.w, q0.z), fmaf(xv.x, q0.y, q0.x));
                float s1 = fmaf(xv.y, fmaf(xv.x, q1.w, q1.z), fmaf(xv.x, q1.y, q1.x));
                float s2 = fmaf(xv.y, fmaf(xv.x, q2.w, q2.z), fmaf(xv.x, q2.y, q2.x));
                float s3 = fmaf(xv.y, fmaf(xv.x, q3.w, q3.z), fmaf(xv.x, q3.y, q3.x));
                xch[r * 256 + j * 32 + lane] =
                    fmaf(xv.w, fmaf(xv.z, s3, s2), fmaf(xv.z, s1, s0));
            }
        }
        __syncwarp();

        // ---- layers 1..4 per row ----
        #pragma unroll
        for (int r = 0; r < G; ++r) {
            float4 a0 = *(const float4*)&xch[r * 256 + lane * 8];
            float4 a1 = *(const float4*)&xch[r * 256 + lane * 8 + 4];
            float z0 = node_eval(sh_t + (256 + 2 * lane) * NODE_F, a0);
            float z1 = node_eval(sh_t + (256 + 2 * lane + 1) * NODE_F, a1);

            float4 b;
            b.x = __shfl_sync(FULL, z0, (lane * 2) & 31);
            b.y = __shfl_sync(FULL, z1, (lane * 2) & 31);
            b.z = __shfl_sync(FULL, z0, (lane * 2 + 1) & 31);
            b.w = __shfl_sync(FULL, z1, (lane * 2 + 1) & 31);
            float w = node_eval(sh_t + (320 + (lane & 15)) * NODE_F, b);

            float4 c;
            c.x = __shfl_sync(FULL, w, (lane * 4 + 0) & 31);
            c.y = __shfl_sync(FULL, w, (lane * 4 + 1) & 31);
            c.z = __shfl_sync(FULL, w, (lane * 4 + 2) & 31);
            c.w = __shfl_sync(FULL, w, (lane * 4 + 3) & 31);
            float v = node_eval(sh_t + (336 + (lane & 3)) * NODE_F, c);

            float4 d;
            d.x = __shfl_sync(FULL, v, 0);
            d.y = __shfl_sync(FULL, v, 1);
            d.z = __shfl_sync(FULL, v, 2);
            d.w = __shfl_sync(FULL, v, 3);
            if (lane == 0)
                out[t * G + r] = node_eval(sh_t + 340 * NODE_F, d);
        }
        __syncwarp();

        t = tn;
        xb = xbn;
    }
}

extern "C" void kernel_launch(void* const* d_in, const int* in_sizes, int n_in,
                              void* d_out, int out_size) {
    const float* x  = (const float*)d_in[0];
    const float* t0 = (const float*)d_in[1];
    const float* t1 = (const float*)d_in[2];
    const float* t2 = (const float*)d_in[3];
    const float* t3 = (const float*)d_in[4];
    const float* t4 = (const float*)d_in[5];
    float* out = (float*)d_out;

    int n_rows = in_sizes[0] / 1024;       // 32768
    int nt = n_rows / G;                   // 8192 tiles

    reset_ctr<<<1, 1>>>();
    cudaFuncSetAttribute(lut_tree_kernel,
                         cudaFuncAttributeMaxDynamicSharedMemorySize, SMEM_B);
    lut_tree_kernel<<<GRID, THREADS, SMEM_B>>>(x, t0, t1, t2, t3, t4, out, nt);
}

// round 10
// speedup vs baseline: 1.7213x; 1.4672x over previous
#include <cuda_runtime.h>

// LUT tree, monomial-coefficient form (R7 base: depth-4 ring, 2 CTAs/SM).
// R10 change: tail layers (1..4) restructured table-outer/rows-inner — each
// tail node's 16 coefs are loaded into registers ONCE and reused across the
// G=4 rows (tail table LDS.128 drops 80 -> 20 per warp-tile).
// Persistent warps steal 4-row tiles; layer-0 x loads double-prefetched through
// a depth-4 register ring (phase-stable: 8 batches % 4 == 0); next tile stolen
// at j==6 so its first 2 batches load under the tail layers.

#define THREADS  256
#define NWARPS   8
#define GRID     296            // 2 CTAs/SM * 148 SMs
#define G        4              // rows per tile

#define NODE_F   20             // 16 coefs + 4 pad -> 80B stride, conflict-free
#define N_NODES  341            // 256+64+16+4+1, by global node id g
#define TTOT     (N_NODES * NODE_F)
#define XCHF     (NWARPS * G * 256)
#define SMEM_B   ((TTOT + XCHF) * 4)   // 27280 + 32768 = 60048 B

typedef unsigned uns;
__device__ uns g_ctr;
__global__ void reset_ctr() { g_ctr = 0; }

// eval with monomial coefs already in registers (q0..q3), inputs xv
__device__ __forceinline__ float node_eval_q(float4 q0, float4 q1, float4 q2,
                                             float4 q3, float4 xv) {
    float s0 = fmaf(xv.y, fmaf(xv.x, q0.w, q0.z), fmaf(xv.x, q0.y, q0.x));
    float s1 = fmaf(xv.y, fmaf(xv.x, q1.w, q1.z), fmaf(xv.x, q1.y, q1.x));
    float s2 = fmaf(xv.y, fmaf(xv.x, q2.w, q2.z), fmaf(xv.x, q2.y, q2.x));
    float s3 = fmaf(xv.y, fmaf(xv.x, q3.w, q3.z), fmaf(xv.x, q3.y, q3.x));
    return fmaf(xv.w, fmaf(xv.z, s3, s2), fmaf(xv.z, s1, s0));
}

__device__ __forceinline__ void load_batch(float4* B, const float4* xb, int j, int lane) {
    #pragma unroll
    for (int r = 0; r < G; ++r)
        B[r] = xb[r * 256 + j * 32 + lane];
}

__global__ void __launch_bounds__(THREADS, 2) lut_tree_kernel(
    const float* __restrict__ x,
    const float* __restrict__ t0, const float* __restrict__ t1,
    const float* __restrict__ t2, const float* __restrict__ t3,
    const float* __restrict__ t4,
    float* __restrict__ out, int nt)
{
    extern __shared__ __align__(16) float smem[];
    float* sh_t = smem;                 // [341][20] monomial coefs
    float* sh_x = smem + TTOT;          // [NWARPS][G][256] exchange

    // ---- loader: fetch 16 corners per node, Mobius transform, store padded ----
    for (int g = threadIdx.x; g < N_NODES; g += THREADS) {
        const float* src; int ln;
        if (g < 256)      { src = t0; ln = g; }
        else if (g < 320) { src = t1; ln = g - 256; }
        else if (g < 336) { src = t2; ln = g - 320; }
        else if (g < 340) { src = t3; ln = g - 336; }
        else              { src = t4; ln = 0; }
        float v[16];
        #pragma unroll
        for (int k = 0; k < 16; ++k) v[k] = src[ln * 16 + k];
        #pragma unroll
        for (int i = 0; i < 4; ++i)
            #pragma unroll
            for (int c = 0; c < 16; ++c)
                if (c & (1 << i)) v[c] -= v[c ^ (1 << i)];
        float* dst = sh_t + g * NODE_F;
        #pragma unroll
        for (int k = 0; k < 16; ++k) dst[k] = v[k];
    }
    __syncthreads();

    const int warp = threadIdx.x >> 5;
    const int lane = threadIdx.x & 31;
    const unsigned FULL = 0xffffffffu;
    float* xch = sh_x + warp * (G * 256);

    uns t;
    if (lane == 0) t = atomicAdd(&g_ctr, 1);
    t = __shfl_sync(FULL, t, 0);

    float4 B[4][G];                      // depth-4 ring: read B[j&3], write B[(j+2)&3]
    const float4* xb = (const float4*)x + (size_t)t * (G * 256);
    if (t < (uns)nt) {
        load_batch(B[0], xb, 0, lane);
        load_batch(B[1], xb, 1, lane);
    }

    while (t < (uns)nt) {
        uns tn = 0xffffffffu;
        const float4* xbn = xb;

        // ---- layer 0: prefetch depth 2, stream crosses into next tile ----
        #pragma unroll
        for (int j = 0; j < 8; ++j) {
            if (j < 6) {
                load_batch(B[(j + 2) & 3], xb, j + 2, lane);
            } else {
                if (j == 6) {
                    if (lane == 0) tn = atomicAdd(&g_ctr, 1);
                    tn = __shfl_sync(FULL, tn, 0);
                    xbn = (const float4*)x + (size_t)tn * (G * 256);
                }
                if (tn < (uns)nt)
                    load_batch(B[(j + 2) & 3], xbn, j - 6, lane);
            }
            const float* cp = sh_t + (j * 32 + lane) * NODE_F;
            float4 q0 = *(const float4*)(cp + 0);
            float4 q1 = *(const float4*)(cp + 4);
            float4 q2 = *(const float4*)(cp + 8);
            float4 q3 = *(const float4*)(cp + 12);
            #pragma unroll
            for (int r = 0; r < G; ++r)
                xch[r * 256 + j * 32 + lane] =
                    node_eval_q(q0, q1, q2, q3, B[j & 3][r]);
        }
        __syncwarp();

        // ---- layers 1..4, table-outer / rows-inner ----
        float z0[G], z1[G], wv[G], vv[G];

        {   // layer 1, node 2*lane
            const float* cp = sh_t + (256 + 2 * lane) * NODE_F;
            float4 q0 = *(const float4*)(cp + 0), q1 = *(const float4*)(cp + 4);
            float4 q2 = *(const float4*)(cp + 8), q3 = *(const float4*)(cp + 12);
            #pragma unroll
            for (int r = 0; r < G; ++r) {
                float4 a = *(const float4*)&xch[r * 256 + lane * 8];
                z0[r] = node_eval_q(q0, q1, q2, q3, a);
            }
        }
        {   // layer 1, node 2*lane+1
            const float* cp = sh_t + (256 + 2 * lane + 1) * NODE_F;
            float4 q0 = *(const float4*)(cp + 0), q1 = *(const float4*)(cp + 4);
            float4 q2 = *(const float4*)(cp + 8), q3 = *(const float4*)(cp + 12);
            #pragma unroll
            for (int r = 0; r < G; ++r) {
                float4 a = *(const float4*)&xch[r * 256 + lane * 8 + 4];
                z1[r] = node_eval_q(q0, q1, q2, q3, a);
            }
        }
        {   // layer 2, node lane&15
            const float* cp = sh_t + (320 + (lane & 15)) * NODE_F;
            float4 q0 = *(const float4*)(cp + 0), q1 = *(const float4*)(cp + 4);
            float4 q2 = *(const float4*)(cp + 8), q3 = *(const float4*)(cp + 12);
            #pragma unroll
            for (int r = 0; r < G; ++r) {
                float4 b;
                b.x = __shfl_sync(FULL, z0[r], (lane * 2) & 31);
                b.y = __shfl_sync(FULL, z1[r], (lane * 2) & 31);
                b.z = __shfl_sync(FULL, z0[r], (lane * 2 + 1) & 31);
                b.w = __shfl_sync(FULL, z1[r], (lane * 2 + 1) & 31);
                wv[r] = node_eval_q(q0, q1, q2, q3, b);
            }
        }
        {   // layer 3, node lane&3
            const float* cp = sh_t + (336 + (lane & 3)) * NODE_F;
            float4 q0 = *(const float4*)(cp + 0), q1 = *(const float4*)(cp + 4);
            float4 q2 = *(const float4*)(cp + 8), q3 = *(const float4*)(cp + 12);
            #pragma unroll
            for (int r = 0; r < G; ++r) {
                float4 c;
                c.x = __shfl_sync(FULL, wv[r], (lane * 4 + 0) & 31);
                c.y = __shfl_sync(FULL, wv[r], (lane * 4 + 1) & 31);
                c.z = __shfl_sync(FULL, wv[r], (lane * 4 + 2) & 31);
                c.w = __shfl_sync(FULL, wv[r], (lane * 4 + 3) & 31);
                vv[r] = node_eval_q(q0, q1, q2, q3, c);
            }
        }
        {   // layer 4, node 340
            const float* cp = sh_t + 340 * NODE_F;
            float4 q0 = *(const float4*)(cp + 0), q1 = *(const float4*)(cp + 4);
            float4 q2 = *(const float4*)(cp + 8), q3 = *(const float4*)(cp + 12);
            #pragma unroll
            for (int r = 0; r < G; ++r) {
                float4 d;
                d.x = __shfl_sync(FULL, vv[r], 0);
                d.y = __shfl_sync(FULL, vv[r], 1);
                d.z = __shfl_sync(FULL, vv[r], 2);
                d.w = __shfl_sync(FULL, vv[r], 3);
                if (lane == 0)
                    out[t * G + r] = node_eval_q(q0, q1, q2, q3, d);
            }
        }
        __syncwarp();

        t = tn;
        xb = xbn;
    }
}

extern "C" void kernel_launch(void* const* d_in, const int* in_sizes, int n_in,
                              void* d_out, int out_size) {
    const float* x  = (const float*)d_in[0];
    const float* t0 = (const float*)d_in[1];
    const float* t1 = (const float*)d_in[2];
    const float* t2 = (const float*)d_in[3];
    const float* t3 = (const float*)d_in[4];
    const float* t4 = (const float*)d_in[5];
    float* out = (float*)d_out;

    int n_rows = in_sizes[0] / 1024;       // 32768
    int nt = n_rows / G;                   // 8192 tiles

    reset_ctr<<<1, 1>>>();
    cudaFuncSetAttribute(lut_tree_kernel,
                         cudaFuncAttributeMaxDynamicSharedMemorySize, SMEM_B);
    lut_tree_kernel<<<GRID, THREADS, SMEM_B>>>(x, t0, t1, t2, t3, t4, out, nt);
}